// round 3
// baseline (speedup 1.0000x reference)
#include <cuda_runtime.h>
#include <math.h>

#define SQ 512
#define HID 768
#define NHEAD 12
#define DHEAD 64
#define BATCH 8
#define NLAYER 12
#define FFDIM 3072
#define ROWS (BATCH*SQ)      /* 4096 */
#define BHT (BATCH*NHEAD)    /* 96   */

/* ---------------- scratch (device globals; no allocation allowed) -------- */
__device__ float g_x[ROWS*HID];
__device__ float g_h1[ROWS*HID];
__device__ float g_tmp[ROWS*HID];
__device__ float g_qb[ROWS*HID];
__device__ float g_kb[ROWS*HID];
__device__ float g_vb[ROWS*HID];
__device__ float g_ctx[ROWS*HID];
__device__ float g_ff[(size_t)ROWS*FFDIM];
__device__ float g_posk[SQ*HID];
__device__ float g_posq[SQ*HID];
__device__ float g_sc[(size_t)BHT*SQ*SQ];
__device__ float g_c2p[(size_t)BHT*SQ*SQ];
__device__ float g_p2c[(size_t)BHT*SQ*SQ];
__device__ int   g_cidx[1023];
__device__ int   g_pidx[1023];

/* ---------------- relative position bucket tables ------------------------ */
__device__ __forceinline__ int log_bucket(int rel) {
    const int mid = 128;
    float abs_pos;
    if (rel < mid && rel > -mid) abs_pos = (float)(mid - 1);
    else                         abs_pos = fabsf((float)rel);
    if (abs_pos <= (float)mid) return rel;
    float denom = (float)log(511.0 / 128.0);
    float log_pos = ceilf(logf(abs_pos / 128.0f) / denom * 127.0f) + 128.0f;
    float sgn = (rel > 0) ? 1.0f : ((rel < 0) ? -1.0f : 0.0f);
    return (int)(log_pos * sgn);
}

__global__ void build_tables_kernel() {
    int i = blockIdx.x * blockDim.x + threadIdx.x;
    if (i >= 1023) return;
    int d = i - 511;                       /* d = q - k */
    int c = log_bucket(d) + 256;           /* c2p index  */
    c = min(max(c, 0), 511);
    int p = 256 - log_bucket(-d);          /* p2c index  */
    p = min(max(p, 0), 511);
    g_cidx[i] = c;
    g_pidx[i] = p;
}

/* ---------------- embedding + masked layernorm --------------------------- */
__global__ void embed_kernel(const float* __restrict__ we, const float* __restrict__ pe,
                             const float* __restrict__ lg, const float* __restrict__ lb,
                             const int* __restrict__ ids, const int* __restrict__ am,
                             float* __restrict__ out) {
    __shared__ float red[256];
    int row = blockIdx.x, tid = threadIdx.x;
    int s = row & (SQ - 1);
    int id = ids[row];
    float v[3];
#pragma unroll
    for (int i = 0; i < 3; i++) {
        int c = tid + i * 256;
        v[i] = we[(size_t)id * HID + c] + pe[(size_t)s * HID + c];
    }
    float sum = v[0] + v[1] + v[2];
    red[tid] = sum; __syncthreads();
    for (int st = 128; st > 0; st >>= 1) { if (tid < st) red[tid] += red[tid + st]; __syncthreads(); }
    float mu = red[0] * (1.0f / HID);
    __syncthreads();
    float s2 = 0.f;
#pragma unroll
    for (int i = 0; i < 3; i++) { float d = v[i] - mu; s2 += d * d; }
    red[tid] = s2; __syncthreads();
    for (int st = 128; st > 0; st >>= 1) { if (tid < st) red[tid] += red[tid + st]; __syncthreads(); }
    float var = red[0] * (1.0f / HID);
    float r = rsqrtf(var + 1e-7f);
    float mf = (float)am[row];
    float* orow = out + (size_t)row * HID;
#pragma unroll
    for (int i = 0; i < 3; i++) {
        int c = tid + i * 256;
        orow[c] = ((v[i] - mu) * r * lg[c] + lb[c]) * mf;
    }
}

/* ---------------- layernorm ---------------------------------------------- */
__global__ void layernorm_kernel(const float* __restrict__ in, const float* __restrict__ lg,
                                 const float* __restrict__ lb, float* __restrict__ out) {
    __shared__ float red[256];
    int row = blockIdx.x, tid = threadIdx.x;
    const float* xr = in + (size_t)row * HID;
    float v[3];
#pragma unroll
    for (int i = 0; i < 3; i++) v[i] = xr[tid + i * 256];
    float sum = v[0] + v[1] + v[2];
    red[tid] = sum; __syncthreads();
    for (int st = 128; st > 0; st >>= 1) { if (tid < st) red[tid] += red[tid + st]; __syncthreads(); }
    float mu = red[0] * (1.0f / HID);
    __syncthreads();
    float s2 = 0.f;
#pragma unroll
    for (int i = 0; i < 3; i++) { float d = v[i] - mu; s2 += d * d; }
    red[tid] = s2; __syncthreads();
    for (int st = 128; st > 0; st >>= 1) { if (tid < st) red[tid] += red[tid + st]; __syncthreads(); }
    float var = red[0] * (1.0f / HID);
    float r = rsqrtf(var + 1e-7f);
    float* orow = out + (size_t)row * HID;
#pragma unroll
    for (int i = 0; i < 3; i++) {
        int c = tid + i * 256;
        orow[c] = (v[i] - mu) * r * lg[c] + lb[c];
    }
}

/* ---------------- batched tiled SGEMM ------------------------------------
   C[M,N] = A[M,K] @ B(,or B^T)[K,N] + bias + residual, optional exact GELU.
   batch z decomposed as (b = z/nh, h = z%nh); per-dim pointer offsets.      */
#define BM 128
#define BN 128
#define BKK 8
#define TM 8
#define TN 8

template<bool TRANSB>
__global__ __launch_bounds__(256, 2)
void gemm_kernel(const float* __restrict__ Abase, const float* __restrict__ Bbase,
                 const float* __restrict__ bias, const float* __restrict__ Rbase,
                 float* __restrict__ Cbase,
                 int M, int N, int K, int lda, int ldb, int ldc,
                 long long sAb, long long sAh, long long sBb, long long sBh,
                 long long sCb, long long sCh, int nh, int flags)
{
    __shared__ float As[BKK][BM];
    __shared__ float Bs[BKK][BN];
    int z = blockIdx.z;
    int bo = z / nh, ho = z - bo * nh;
    const float* A = Abase + (size_t)bo * sAb + (size_t)ho * sAh;
    const float* B = Bbase + (size_t)bo * sBb + (size_t)ho * sBh;
    float*       C = Cbase + (size_t)bo * sCb + (size_t)ho * sCh;

    int tid = threadIdx.x;
    int m0 = blockIdx.y * BM;
    int n0 = blockIdx.x * BN;

    int lRow = tid >> 1;            /* 0..127 */
    int lCol = (tid & 1) << 2;      /* 0 or 4 */
    int bRow = tid >> 5;            /* 0..7   */
    int bCol = (tid & 31) << 2;     /* 0..124 */

    int tx = tid & 15, ty = tid >> 4;
    int tm = ty * TM, tn = tx * TN;

    float acc[TM][TN];
#pragma unroll
    for (int i = 0; i < TM; i++)
#pragma unroll
        for (int j = 0; j < TN; j++) acc[i][j] = 0.f;

    for (int k0 = 0; k0 < K; k0 += BKK) {
        {
            float4 va = make_float4(0.f, 0.f, 0.f, 0.f);
            int gm = m0 + lRow;
            if (gm < M) va = *reinterpret_cast<const float4*>(A + (size_t)gm * lda + k0 + lCol);
            As[lCol + 0][lRow] = va.x; As[lCol + 1][lRow] = va.y;
            As[lCol + 2][lRow] = va.z; As[lCol + 3][lRow] = va.w;
        }
        if (TRANSB) {
            float4 vb = make_float4(0.f, 0.f, 0.f, 0.f);
            int gn = n0 + lRow;
            if (gn < N) vb = *reinterpret_cast<const float4*>(B + (size_t)gn * ldb + k0 + lCol);
            Bs[lCol + 0][lRow] = vb.x; Bs[lCol + 1][lRow] = vb.y;
            Bs[lCol + 2][lRow] = vb.z; Bs[lCol + 3][lRow] = vb.w;
        } else {
            float4 vb = make_float4(0.f, 0.f, 0.f, 0.f);
            int gn = n0 + bCol;
            if (gn < N) vb = *reinterpret_cast<const float4*>(B + (size_t)(k0 + bRow) * ldb + gn);
            *reinterpret_cast<float4*>(&Bs[bRow][bCol]) = vb;
        }
        __syncthreads();
#pragma unroll
        for (int kk = 0; kk < BKK; kk++) {
            float ra[TM], rb[TN];
#pragma unroll
            for (int i = 0; i < TM; i += 4)
                *reinterpret_cast<float4*>(ra + i) = *reinterpret_cast<const float4*>(&As[kk][tm + i]);
#pragma unroll
            for (int j = 0; j < TN; j += 4)
                *reinterpret_cast<float4*>(rb + j) = *reinterpret_cast<const float4*>(&Bs[kk][tn + j]);
#pragma unroll
            for (int i = 0; i < TM; i++)
#pragma unroll
                for (int j = 0; j < TN; j++) acc[i][j] += ra[i] * rb[j];
        }
        __syncthreads();
    }

    bool doGelu = (flags & 1) != 0;
    bool hasR   = (flags & 2) != 0;
#pragma unroll
    for (int i = 0; i < TM; i++) {
        int gm = m0 + tm + i;
        if (gm >= M) continue;
#pragma unroll
        for (int j = 0; j < TN; j++) {
            int gn = n0 + tn + j;
            if (gn >= N) continue;
            float c = acc[i][j];
            if (bias) c += bias[gn];
            if (hasR) c += Rbase[(size_t)gm * ldc + gn];
            if (doGelu) c = 0.5f * c * (1.0f + erff(c * 0.70710678118654752f));
            C[(size_t)gm * ldc + gn] = c;
        }
    }
}

/* ---------------- disentangled-bias gather + masked softmax -------------- */
__global__ void attn_softmax_kernel(float* __restrict__ sc, const float* __restrict__ c2p,
                                    const float* __restrict__ p2c, const int* __restrict__ am) {
    int q = blockIdx.x, bh = blockIdx.y;
    int b = bh / NHEAD;
    const float inv_scale = 0.07216878364870322f;  /* 1/sqrt(3*DH) */
    float* row = sc + ((size_t)bh * SQ + q) * SQ;
    const float* crow = c2p + ((size_t)bh * SQ + q) * SQ;
    const float* pbh  = p2c + (size_t)bh * SQ * SQ;
    int tid = threadIdx.x;
    bool mq = am[b * SQ + q] != 0;

    float v[2]; bool ok[2];
    float lmax = -3.402823466e38f;
#pragma unroll
    for (int i = 0; i < 2; i++) {
        int k = tid + i * 256;
        int di = q - k + 511;
        float s = (row[k] + crow[g_cidx[di]] + pbh[(size_t)k * SQ + g_pidx[di]]) * inv_scale;
        ok[i] = mq && (am[b * SQ + k] != 0);
        v[i] = ok[i] ? s : -3.402823466e38f;
        lmax = fmaxf(lmax, v[i]);
    }
    __shared__ float red[256];
    red[tid] = lmax; __syncthreads();
    for (int st = 128; st > 0; st >>= 1) { if (tid < st) red[tid] = fmaxf(red[tid], red[tid + st]); __syncthreads(); }
    float m = red[0]; __syncthreads();
    float ls = 0.f;
#pragma unroll
    for (int i = 0; i < 2; i++) { float e = expf(v[i] - m); v[i] = e; ls += e; }
    red[tid] = ls; __syncthreads();
    for (int st = 128; st > 0; st >>= 1) { if (tid < st) red[tid] += red[tid + st]; __syncthreads(); }
    float inv = 1.0f / red[0];
#pragma unroll
    for (int i = 0; i < 2; i++) {
        int k = tid + i * 256;
        row[k] = ok[i] ? v[i] * inv : 0.0f;
    }
}

/* ---------------- host orchestration ------------------------------------- */
extern "C" void kernel_launch(void* const* d_in, const int* in_sizes, int n_in,
                              void* d_out, int out_size) {
    const float* word_emb = (const float*)d_in[0];
    const float* pos_emb  = (const float*)d_in[1];
    const float* emb_ln_g = (const float*)d_in[2];
    const float* emb_ln_b = (const float*)d_in[3];
    const float* rel_emb  = (const float*)d_in[4];
    const float* Wq = (const float*)d_in[5];
    const float* bq = (const float*)d_in[6];
    const float* Wk = (const float*)d_in[7];
    const float* bk = (const float*)d_in[8];
    const float* Wv = (const float*)d_in[9];
    const float* bv = (const float*)d_in[10];
    const float* Wo = (const float*)d_in[11];
    const float* bo = (const float*)d_in[12];
    const float* ln1_g = (const float*)d_in[13];
    const float* ln1_b = (const float*)d_in[14];
    const float* Wi = (const float*)d_in[15];
    const float* bi = (const float*)d_in[16];
    const float* Wo2 = (const float*)d_in[17];
    const float* bo2 = (const float*)d_in[18];
    const float* ln2_g = (const float*)d_in[19];
    const float* ln2_b = (const float*)d_in[20];
    const int* input_ids = (const int*)d_in[21];
    const int* attn_mask = (const int*)d_in[22];
    float* out = (float*)d_out;

    float *x, *h1, *tmp, *qb, *kb, *vb, *ctx, *ff, *posk, *posq, *sc, *c2p, *p2c;
    cudaGetSymbolAddress((void**)&x,    g_x);
    cudaGetSymbolAddress((void**)&h1,   g_h1);
    cudaGetSymbolAddress((void**)&tmp,  g_tmp);
    cudaGetSymbolAddress((void**)&qb,   g_qb);
    cudaGetSymbolAddress((void**)&kb,   g_kb);
    cudaGetSymbolAddress((void**)&vb,   g_vb);
    cudaGetSymbolAddress((void**)&ctx,  g_ctx);
    cudaGetSymbolAddress((void**)&ff,   g_ff);
    cudaGetSymbolAddress((void**)&posk, g_posk);
    cudaGetSymbolAddress((void**)&posq, g_posq);
    cudaGetSymbolAddress((void**)&sc,   g_sc);
    cudaGetSymbolAddress((void**)&c2p,  g_c2p);
    cudaGetSymbolAddress((void**)&p2c,  g_p2c);

    dim3 blk(256);
    const long long SH = (long long)SQ * HID;       /* per-batch row stride */
    const long long SS = (long long)SQ * SQ;        /* per-head score tile  */
    const long long HSS = (long long)NHEAD * SS;    /* per-batch score blk  */

    build_tables_kernel<<<1, 1024>>>();
    embed_kernel<<<ROWS, 256>>>(word_emb, pos_emb, emb_ln_g, emb_ln_b, input_ids, attn_mask, x);

    for (int l = 0; l < NLAYER; l++) {
        const float* Wq_l = Wq + (size_t)l * HID * HID;
        const float* Wk_l = Wk + (size_t)l * HID * HID;
        const float* Wv_l = Wv + (size_t)l * HID * HID;
        const float* Wo_l = Wo + (size_t)l * HID * HID;
        const float* Wi_l = Wi + (size_t)l * HID * FFDIM;
        const float* Wo2_l = Wo2 + (size_t)l * FFDIM * HID;
        const float* bq_l = bq + (size_t)l * HID;
        const float* bk_l = bk + (size_t)l * HID;
        const float* bv_l = bv + (size_t)l * HID;
        const float* bo_l = bo + (size_t)l * HID;
        const float* bi_l = bi + (size_t)l * FFDIM;
        const float* bo2_l = bo2 + (size_t)l * HID;

        /* Q, K, V projections: [4096,768] = x @ W + b */
        gemm_kernel<false><<<dim3(6, 32, 1), blk>>>(x, Wq_l, bq_l, nullptr, qb,
            ROWS, HID, HID, HID, HID, HID, 0, 0, 0, 0, 0, 0, 1, 0);
        gemm_kernel<false><<<dim3(6, 32, 1), blk>>>(x, Wk_l, bk_l, nullptr, kb,
            ROWS, HID, HID, HID, HID, HID, 0, 0, 0, 0, 0, 0, 1, 0);
        gemm_kernel<false><<<dim3(6, 32, 1), blk>>>(x, Wv_l, bv_l, nullptr, vb,
            ROWS, HID, HID, HID, HID, HID, 0, 0, 0, 0, 0, 0, 1, 0);

        /* shared-key / shared-query position projections: [512,768] */
        gemm_kernel<false><<<dim3(6, 4, 1), blk>>>(rel_emb, Wk_l, bk_l, nullptr, posk,
            SQ, HID, HID, HID, HID, HID, 0, 0, 0, 0, 0, 0, 1, 0);
        gemm_kernel<false><<<dim3(6, 4, 1), blk>>>(rel_emb, Wq_l, bq_l, nullptr, posq,
            SQ, HID, HID, HID, HID, HID, 0, 0, 0, 0, 0, 0, 1, 0);

        /* raw scores QK^T per (b,h): [512,512,64] x 96 */
        gemm_kernel<true><<<dim3(4, 4, BHT), blk>>>(qb, kb, nullptr, nullptr, sc,
            SQ, SQ, DHEAD, HID, HID, SQ, SH, DHEAD, SH, DHEAD, HSS, SS, NHEAD, 0);
        /* c2p: Q @ pos_k^T */
        gemm_kernel<true><<<dim3(4, 4, BHT), blk>>>(qb, posk, nullptr, nullptr, c2p,
            SQ, SQ, DHEAD, HID, HID, SQ, SH, DHEAD, 0, DHEAD, HSS, SS, NHEAD, 0);
        /* p2c: K @ pos_q^T */
        gemm_kernel<true><<<dim3(4, 4, BHT), blk>>>(kb, posq, nullptr, nullptr, p2c,
            SQ, SQ, DHEAD, HID, HID, SQ, SH, DHEAD, 0, DHEAD, HSS, SS, NHEAD, 0);

        /* gather rel-pos terms + mask + softmax (in-place on sc) */
        attn_softmax_kernel<<<dim3(SQ, BHT), 256>>>(sc, c2p, p2c, attn_mask);

        /* ctx = probs @ V : [512,64,512] x 96, scattered into [B*S,H] layout */
        gemm_kernel<false><<<dim3(1, 4, BHT), blk>>>(sc, vb, nullptr, nullptr, ctx,
            SQ, DHEAD, SQ, SQ, HID, HID, HSS, SS, SH, DHEAD, SH, DHEAD, NHEAD, 0);

        /* output projection + residual, then LN -> h1 */
        gemm_kernel<false><<<dim3(6, 32, 1), blk>>>(ctx, Wo_l, bo_l, x, tmp,
            ROWS, HID, HID, HID, HID, HID, 0, 0, 0, 0, 0, 0, 1, 2);
        layernorm_kernel<<<ROWS, 256>>>(tmp, ln1_g + (size_t)l * HID, ln1_b + (size_t)l * HID, h1);

        /* FFN: gelu(h1 @ Wi + bi) @ Wo2 + bo2 + h1, then LN */
        gemm_kernel<false><<<dim3(24, 32, 1), blk>>>(h1, Wi_l, bi_l, nullptr, ff,
            ROWS, FFDIM, HID, HID, FFDIM, FFDIM, 0, 0, 0, 0, 0, 0, 1, 1);
        gemm_kernel<false><<<dim3(6, 32, 1), blk>>>(ff, Wo2_l, bo2_l, h1, tmp,
            ROWS, HID, FFDIM, FFDIM, HID, HID, 0, 0, 0, 0, 0, 0, 1, 2);
        layernorm_kernel<<<ROWS, 256>>>(tmp, ln2_g + (size_t)l * HID, ln2_b + (size_t)l * HID,
                                        (l == NLAYER - 1) ? out : x);
    }
}